// round 17
// baseline (speedup 1.0000x reference)
#include <cuda_runtime.h>
#include <cuda_bf16.h>
#include <cstddef>
#include <cstdint>

#define SEQ   2048
#define BATCH 64
#define NIN   256
#define HID   256

#define RNN_BLOCKS  128                 // 64 clusters x 2 CTAs
#define HEAD_CHUNKS 704                 // chunks done by the head kernel
#define PROJ_CHUNKS 1024                // 1 chunk = 128 m-rows = 2 timesteps
#define TAIL_CHUNKS (PROJ_CHUNKS - HEAD_CHUNKS)        // 320
#define TOTAL_BLOCKS (RNN_BLOCKS + TAIL_CHUNKS * 4)    // 1408

// Scratch
__device__ float g_xp[(size_t)SEQ * BATCH * HID];
__device__ int   g_done[PROJ_CHUNKS];

// ---------------------------------------------------------------------------
// helpers
// ---------------------------------------------------------------------------
__device__ __forceinline__ uint32_t smem_u32(const void* p) {
    uint32_t a;
    asm("{ .reg .u64 t; cvta.to.shared.u64 t, %1; cvt.u32.u64 %0, t; }"
        : "=r"(a) : "l"(p));
    return a;
}

#define FMA2(acc, a, b)                                             \
    asm("fma.rn.f32x2 %0, %1, %2, %3;"                              \
        : "=l"(acc) : "l"(a), "l"(b), "l"(acc))

__device__ __forceinline__ unsigned long long pack_dup(float x) {
    unsigned long long d;
    asm("mov.b64 %0, {%1, %1};" : "=l"(d) : "r"(__float_as_uint(x)));
    return d;
}
__device__ __forceinline__ float2 unpack2(unsigned long long v) {
    float2 r;
    asm("mov.b64 {%0, %1}, %2;" : "=f"(r.x), "=f"(r.y) : "l"(v));
    return r;
}

__device__ __forceinline__ void mbar_wait(uint32_t mbar, uint32_t parity) {
    asm volatile(
        "{\n\t"
        ".reg .pred P;\n"
        "$WL%=:\n\t"
        "mbarrier.try_wait.parity.acquire.cta.shared::cta.b64 P, [%0], %1, 0x989680;\n\t"
        "@!P bra $WL%=;\n\t"
        "}"
        :: "r"(mbar), "r"(parity) : "memory");
}

__device__ __forceinline__ int ld_acquire_gpu(const int* p) {
    int v;
    asm volatile("ld.acquire.gpu.b32 %0, [%1];" : "=r"(v) : "l"(p) : "memory");
    return v;
}

// fast tanh: 1 - 2/(e^{2x}+1), MUFU-based, ~1e-6 rel err, saturates correctly.
__device__ __forceinline__ float ftanh(float x) {
    float e = __expf(2.f * x);
    return 1.f - __fdividef(2.f, e + 1.f);
}

// ---------------------------------------------------------------------------
// Kernel 1: projection HEAD — re-blocked GEMM.
//   BM=128, BN=128, BK=16, 256 threads, 8x8 register tile (f32x2 accs).
//   LDS:FMA2 ratio 1:8 (was 1:5.3) -> off the crossbar wall.
//   grid (HEAD_CHUNKS, 2). Block (0,0) zeroes the tail flags.
// ---------------------------------------------------------------------------
__global__ void __launch_bounds__(256, 2) head_kernel(
    const float* __restrict__ X,
    const float* __restrict__ W,
    const float* __restrict__ b_ih,
    const float* __restrict__ b_hh)
{
    constexpr int BM = 128, BN = 128, BK = 16;
    __shared__ float As[BK][BM + 8];     // pad 8: conflict-free transpose store
    __shared__ float Bs[BK][BN + 8];

    const int tid = threadIdx.x;

    if (blockIdx.x == 0 && blockIdx.y == 0) {
        for (int i = tid; i < PROJ_CHUNKS; i += 256) g_done[i] = 0;
        __threadfence();
    }

    const int m0 = blockIdx.x * BM;
    const int n0 = blockIdx.y * BN;
    const int tx = tid & 15;             // n group (8 wide)
    const int ty = tid >> 4;             // m group (8 wide)

    unsigned long long acc2[4][8];       // [m-pair][n]
#pragma unroll
    for (int i = 0; i < 4; i++)
#pragma unroll
        for (int j = 0; j < 8; j++) acc2[i][j] = 0ULL;

    for (int kb = 0; kb < NIN; kb += BK) {
        // A tile: 128 rows x 16 k = 512 float4, 2 per thread, transpose
#pragma unroll
        for (int it = 0; it < 2; it++) {
            int idx = tid + it * 256;
            int r   = idx >> 2;          // 0..127
            int c4  = idx & 3;           // 0..3
            float4 v = *(const float4*)&X[(size_t)(m0 + r) * NIN + kb + c4 * 4];
            As[c4 * 4 + 0][r] = v.x;
            As[c4 * 4 + 1][r] = v.y;
            As[c4 * 4 + 2][r] = v.z;
            As[c4 * 4 + 3][r] = v.w;
        }
        // B tile: 128 rows x 16 k = 512 float4, 2 per thread, transpose
#pragma unroll
        for (int it = 0; it < 2; it++) {
            int idx = tid + it * 256;
            int r   = idx >> 2;
            int c4  = idx & 3;
            float4 v = *(const float4*)&W[(size_t)(n0 + r) * NIN + kb + c4 * 4];
            Bs[c4 * 4 + 0][r] = v.x;
            Bs[c4 * 4 + 1][r] = v.y;
            Bs[c4 * 4 + 2][r] = v.z;
            Bs[c4 * 4 + 3][r] = v.w;
        }
        __syncthreads();

#pragma unroll
        for (int k = 0; k < BK; k++) {
            // a: 8 m-values as 4 u64 pairs (two LDS.128)
            const ulonglong2* ap = (const ulonglong2*)&As[k][ty * 8];
            ulonglong2 am0 = ap[0];
            ulonglong2 am1 = ap[1];
            // b: 8 n-values (two LDS.128), duplicated into u64 lanes
            float4 bv0 = *(const float4*)&Bs[k][tx * 8];
            float4 bv1 = *(const float4*)&Bs[k][tx * 8 + 4];
            unsigned long long bd[8];
            bd[0] = pack_dup(bv0.x); bd[1] = pack_dup(bv0.y);
            bd[2] = pack_dup(bv0.z); bd[3] = pack_dup(bv0.w);
            bd[4] = pack_dup(bv1.x); bd[5] = pack_dup(bv1.y);
            bd[6] = pack_dup(bv1.z); bd[7] = pack_dup(bv1.w);

#pragma unroll
            for (int j = 0; j < 8; j++) FMA2(acc2[0][j], am0.x, bd[j]);
#pragma unroll
            for (int j = 0; j < 8; j++) FMA2(acc2[1][j], am0.y, bd[j]);
#pragma unroll
            for (int j = 0; j < 8; j++) FMA2(acc2[2][j], am1.x, bd[j]);
#pragma unroll
            for (int j = 0; j < 8; j++) FMA2(acc2[3][j], am1.y, bd[j]);
        }
        __syncthreads();
    }

    // epilogue: bias (8 n's) + stores (8 rows x 8 n as 2 float4 each)
    const int nbase = n0 + tx * 8;
    float4 bl0 = *(const float4*)&b_ih[nbase];
    float4 bl1 = *(const float4*)&b_ih[nbase + 4];
    float4 bh0 = *(const float4*)&b_hh[nbase];
    float4 bh1 = *(const float4*)&b_hh[nbase + 4];
    float bias[8] = { bl0.x + bh0.x, bl0.y + bh0.y, bl0.z + bh0.z, bl0.w + bh0.w,
                      bl1.x + bh1.x, bl1.y + bh1.y, bl1.z + bh1.z, bl1.w + bh1.w };

#pragma unroll
    for (int mi = 0; mi < 4; mi++) {
        float lo[8], hi[8];
#pragma unroll
        for (int j = 0; j < 8; j++) {
            float2 c = unpack2(acc2[mi][j]);
            lo[j] = c.x + bias[j];
            hi[j] = c.y + bias[j];
        }
        int mA = m0 + ty * 8 + 2 * mi;
        float* r0 = &g_xp[(size_t)mA * HID + nbase];
        float* r1 = &g_xp[(size_t)(mA + 1) * HID + nbase];
        ((float4*)r0)[0] = make_float4(lo[0], lo[1], lo[2], lo[3]);
        ((float4*)r0)[1] = make_float4(lo[4], lo[5], lo[6], lo[7]);
        ((float4*)r1)[0] = make_float4(hi[0], hi[1], hi[2], hi[3]);
        ((float4*)r1)[1] = make_float4(hi[4], hi[5], hi[6], hi[7]);
    }
}

// ---------------------------------------------------------------------------
// Kernel 2 (fused): R12/R16-proven champion structure (H=704).
//   blocks [0,128): the R2 rnn (64 clusters x 2 CTAs) + t0 flag gate + ftanh.
//   blocks [128, TOTAL): projection TAIL tiles (old proven 128x64 shape)
//     for chunks [704,1024) on the ~20 SMs the rnn leaves free.
// ---------------------------------------------------------------------------
__global__ void __launch_bounds__(256, 1) __cluster_dims__(2, 1, 1)
fused_kernel(const float* __restrict__ X,
             const float* __restrict__ W_ih,
             const float* __restrict__ W_hh,
             const float* __restrict__ b_ih,
             const float* __restrict__ b_hh,
             float* __restrict__ out)
{
    __shared__ float sm_h[2][256];        // rnn: double-buffered h
    __shared__ float sm_p[2][256];        // rnn: peer partials
    __shared__ __align__(8) unsigned long long sm_mbar[2];
    __shared__ float sm_As[32][132];      // proj tail tiles
    __shared__ float sm_Bs[32][68];

    const int t = threadIdx.x;

    if (blockIdx.x >= RNN_BLOCKS) {
        // ===================== PROJECTION TAIL =====================
        const int pb    = blockIdx.x - RNN_BLOCKS;
        const int chunk = HEAD_CHUNKS + (pb >> 2);   // ascending completion
        const int ntile = pb & 3;
        const int m0    = chunk * 128;
        const int n0    = ntile * 64;
        const int tx    = t & 15;
        const int ty    = t >> 4;

        unsigned long long acc2[4][4];
#pragma unroll
        for (int i = 0; i < 4; i++)
#pragma unroll
            for (int j = 0; j < 4; j++) acc2[i][j] = 0ULL;

        for (int kb = 0; kb < NIN; kb += 32) {
#pragma unroll
            for (int it = 0; it < 4; it++) {
                int idx = t + it * 256;
                int r   = idx >> 3;
                int c4  = idx & 7;
                float4 v = *(const float4*)&X[(size_t)(m0 + r) * NIN + kb + c4 * 4];
                sm_As[c4 * 4 + 0][r] = v.x;
                sm_As[c4 * 4 + 1][r] = v.y;
                sm_As[c4 * 4 + 2][r] = v.z;
                sm_As[c4 * 4 + 3][r] = v.w;
            }
#pragma unroll
            for (int it = 0; it < 2; it++) {
                int idx = t + it * 256;
                int r   = idx >> 3;
                int c4  = idx & 7;
                float4 v = *(const float4*)&W_ih[(size_t)(n0 + r) * NIN + kb + c4 * 4];
                sm_Bs[c4 * 4 + 0][r] = v.x;
                sm_Bs[c4 * 4 + 1][r] = v.y;
                sm_Bs[c4 * 4 + 2][r] = v.z;
                sm_Bs[c4 * 4 + 3][r] = v.w;
            }
            __syncthreads();
#pragma unroll
            for (int k = 0; k < 32; k++) {
                const ulonglong2* ap = (const ulonglong2*)&sm_As[k][ty * 8];
                ulonglong2 av0 = ap[0];
                ulonglong2 av1 = ap[1];
                float4 bv = *(const float4*)&sm_Bs[k][tx * 4];
                unsigned long long bd0 = pack_dup(bv.x);
                unsigned long long bd1 = pack_dup(bv.y);
                unsigned long long bd2 = pack_dup(bv.z);
                unsigned long long bd3 = pack_dup(bv.w);
                FMA2(acc2[0][0], av0.x, bd0); FMA2(acc2[0][1], av0.x, bd1);
                FMA2(acc2[0][2], av0.x, bd2); FMA2(acc2[0][3], av0.x, bd3);
                FMA2(acc2[1][0], av0.y, bd0); FMA2(acc2[1][1], av0.y, bd1);
                FMA2(acc2[1][2], av0.y, bd2); FMA2(acc2[1][3], av0.y, bd3);
                FMA2(acc2[2][0], av1.x, bd0); FMA2(acc2[2][1], av1.x, bd1);
                FMA2(acc2[2][2], av1.x, bd2); FMA2(acc2[2][3], av1.x, bd3);
                FMA2(acc2[3][0], av1.y, bd0); FMA2(acc2[3][1], av1.y, bd1);
                FMA2(acc2[3][2], av1.y, bd2); FMA2(acc2[3][3], av1.y, bd3);
            }
            __syncthreads();
        }

        const int nbase = n0 + tx * 4;
        float4 bias;
        bias.x = b_ih[nbase + 0] + b_hh[nbase + 0];
        bias.y = b_ih[nbase + 1] + b_hh[nbase + 1];
        bias.z = b_ih[nbase + 2] + b_hh[nbase + 2];
        bias.w = b_ih[nbase + 3] + b_hh[nbase + 3];
#pragma unroll
        for (int mi = 0; mi < 4; mi++) {
            float2 c0 = unpack2(acc2[mi][0]);
            float2 c1 = unpack2(acc2[mi][1]);
            float2 c2 = unpack2(acc2[mi][2]);
            float2 c3 = unpack2(acc2[mi][3]);
            int mA = m0 + ty * 8 + 2 * mi;
            float4 v0 = { c0.x + bias.x, c1.x + bias.y, c2.x + bias.z, c3.x + bias.w };
            float4 v1 = { c0.y + bias.x, c1.y + bias.y, c2.y + bias.z, c3.y + bias.w };
            *(float4*)&g_xp[(size_t)mA * HID + nbase]       = v0;
            *(float4*)&g_xp[(size_t)(mA + 1) * HID + nbase] = v1;
        }

        __syncthreads();
        if (t == 0) {
            __threadfence();
            atomicAdd(&g_done[chunk], 1);
        }
        return;
    }

    // ===================== RECURRENCE (R2/R12 verbatim + ftanh) ============
    const uint32_t rank = blockIdx.x & 1;
    const int      b    = blockIdx.x >> 1;
    const int      k0   = rank << 7;

    unsigned long long w2[64];
    {
        const ulonglong2* wp = (const ulonglong2*)(W_hh + (size_t)t * HID + k0);
#pragma unroll
        for (int i = 0; i < 32; i++) {
            ulonglong2 v = wp[i];
            w2[2 * i]     = v.x;
            w2[2 * i + 1] = v.y;
        }
    }

    sm_h[0][t] = 0.f;
    if (t == 0) {
        asm volatile("mbarrier.init.shared.b64 [%0], 1;"
                     :: "r"(smem_u32(&sm_mbar[0])) : "memory");
        asm volatile("mbarrier.init.shared.b64 [%0], 1;"
                     :: "r"(smem_u32(&sm_mbar[1])) : "memory");
    }
    __syncthreads();
    asm volatile("barrier.cluster.arrive.aligned;" ::: "memory");
    asm volatile("barrier.cluster.wait.aligned;"   ::: "memory");

    const uint32_t peer  = rank ^ 1u;
    const uint32_t p_loc = smem_u32(&sm_p[0][0]);
    const uint32_t m_loc = smem_u32(&sm_mbar[0]);
    uint32_t p_rem, m_rem;
    asm("mapa.shared::cluster.u32 %0, %1, %2;"
        : "=r"(p_rem) : "r"(p_loc), "r"(peer));
    asm("mapa.shared::cluster.u32 %0, %1, %2;"
        : "=r"(m_rem) : "r"(m_loc), "r"(peer));

    // xp window (3 deep). Chunks 0..2 guaranteed by the head kernel.
    const float* xpb = g_xp + (size_t)b * HID + t;
    float xp0 = xpb[0];
    float xp1 = xpb[(size_t)1 * BATCH * HID];
    float xp2 = xpb[(size_t)2 * BATCH * HID];

    float* outp = out + (size_t)b * HID + t;
    const bool own = ((uint32_t)(t >> 7) == rank);
    int wm = HEAD_CHUNKS;                 // t0's flag watermark (tail only)

#pragma unroll 1
    for (int s = 0; s < SEQ; s++) {
        const uint32_t bufsel = (uint32_t)(s & 1);
        const uint32_t parity = (uint32_t)((s >> 1) & 1);

        // prefetch xp[s+3] (covered by the gate's 16-step lead)
        float xpn = 0.f;
        if (s + 3 < SEQ) xpn = xpb[(size_t)(s + 3) * BATCH * HID];

        // ---- dot over own k-half: 32 LDS.128 + 64 FFMA2 ----
        const ulonglong2* hp = (const ulonglong2*)(&sm_h[bufsel][0] + k0);
        unsigned long long a0 = 0ULL, a1 = 0ULL, a2 = 0ULL, a3 = 0ULL;
#pragma unroll
        for (int i = 0; i < 16; i++) {
            ulonglong2 h01 = hp[2 * i];
            ulonglong2 h23 = hp[2 * i + 1];
            FMA2(a0, w2[4 * i + 0], h01.x);
            FMA2(a1, w2[4 * i + 1], h01.y);
            FMA2(a2, w2[4 * i + 2], h23.x);
            FMA2(a3, w2[4 * i + 3], h23.y);
        }
        float2 f0 = unpack2(a0), f1 = unpack2(a1);
        float2 f2 = unpack2(a2), f3 = unpack2(a3);
        float mine = ((f0.x + f0.y) + (f1.x + f1.y))
                   + ((f2.x + f2.y) + (f3.x + f3.y));

        // ---- send partial to peer (all 256 threads; R2-proven) ----
        asm volatile(
            "st.async.shared::cluster.mbarrier::complete_tx::bytes.b32 "
            "[%0], %1, [%2];"
            :: "r"(p_rem + (bufsel << 10) + ((uint32_t)t << 2)),
               "r"(__float_as_uint(mine)),
               "r"(m_rem + bufsel * 8)
            : "memory");

        if (t == 0) {
            asm volatile(
                "mbarrier.arrive.expect_tx.shared.b64 _, [%0], 1024;"
                :: "r"(m_loc + bufsel * 8) : "memory");
            // flag gate: keep 16-step lead over the xp prefetches (tail only)
            if ((s & 15) == 0) {
                int need = (s + 35) >> 1;
                if (need > PROJ_CHUNKS - 1) need = PROJ_CHUNKS - 1;
                while (wm <= need) {
                    if (ld_acquire_gpu(&g_done[wm]) >= 4) wm++;
                }
            }
        }

        mbar_wait(m_loc + bufsel * 8, parity);

        // ---- combine (deterministic order), ftanh, publish ----
        float theirs = sm_p[bufsel][t];
        float lo = rank ? theirs : mine;
        float hi = rank ? mine   : theirs;
        float hv = ftanh(xp0 + (lo + hi));
        if (own) {
            sm_h[bufsel ^ 1u][t] = hv;
            outp[(size_t)s * BATCH * HID] = hv;
        }

        xp0 = xp1; xp1 = xp2; xp2 = xpn;
        __syncthreads();
    }

    asm volatile("barrier.cluster.arrive.aligned;" ::: "memory");
    asm volatile("barrier.cluster.wait.aligned;"   ::: "memory");
}

// ---------------------------------------------------------------------------
extern "C" void kernel_launch(void* const* d_in, const int* in_sizes, int n_in,
                              void* d_out, int out_size)
{
    const float* input = (const float*)d_in[0];   // [SEQ, BATCH, NIN]
    const float* W_ih  = (const float*)d_in[1];   // [HID, NIN]
    const float* W_hh  = (const float*)d_in[2];   // [HID, HID]
    const float* b_ih  = (const float*)d_in[3];   // [HID]
    const float* b_hh  = (const float*)d_in[4];   // [HID]
    float* out = (float*)d_out;                   // [SEQ*BATCH, HID]

    // 1) projection HEAD: chunks [0, 704), BN=128 tiles (2 per chunk);
    //    block(0,0) zeroes the tail flags
    dim3 hgrid(HEAD_CHUNKS, 2);
    head_kernel<<<hgrid, 256>>>(input, W_ih, b_ih, b_hh);

    // 2) fused: rnn (128 CTAs, 64 clusters, placed FIRST by the CLC map)
    //    + projection TAIL (chunks 704..1023) on the leftover ~20 SMs
    fused_kernel<<<TOTAL_BLOCKS, 256>>>(input, W_ih, W_hh, b_ih, b_hh, out);
}